// round 14
// baseline (speedup 1.0000x reference)
#include <cuda_runtime.h>
#include <math.h>

constexpr int B = 16, C = 80, H = 64, W = 64, K = 20;
constexpr int HW = H * W;          // 4096
constexpr int NPAIR = B * K;       // 320
constexpr int NT = 512;            // threads per block (16 warps)
// PEAK_TEMP = 10: sigmoid(10*(v-thr)) = 0.5*tanh(5*(v-thr)) + 0.5

__device__ float g_partial[NPAIR];
__device__ unsigned int g_done = 0;   // completion counter (reset by last block)

__device__ __forceinline__ float tanh_fast(float x) {
    float y;
    asm("tanh.approx.f32 %0, %1;" : "=f"(y) : "f"(x));
    return y;
}

// Argmax key packing: cam values are >= 0, so raw float bits are monotonic.
// key = (val_bits << 32) | (0xFFFFFFFF - idx): max key == max val, ties -> min idx
// (== first occurrence, matching jnp.argmax). Init key 0 decodes to a huge idx
// that loses any tie; if the mask were empty the gather index clamps safely.
__device__ __forceinline__ unsigned long long pack_key(float v, int idx) {
    return ((unsigned long long)__float_as_uint(v) << 32) |
           (unsigned long long)(0xFFFFFFFFu - (unsigned int)idx);
}
__device__ __forceinline__ int key_idx(unsigned long long k) {
    return (int)(0xFFFFFFFFu - (unsigned int)(k & 0xFFFFFFFFull));
}

// One block per (b,k) pair; LAST block to finish also does the final sum.
__global__ __launch_bounds__(NT) void fused_kernel(
    const float* __restrict__ cam,         // [B,C,H,W]
    const float* __restrict__ pred_boxes,  // [B,C,H,W,4]
    const float* __restrict__ gt_boxes,    // [B,K,4]
    const int*   __restrict__ gt_labels,   // [B,K]
    const float* __restrict__ threshold,   // [1]
    float* __restrict__ out, int out_size)
{
    const int pair = blockIdx.x;
    const int b    = pair / K;
    const int lab  = __ldg(&gt_labels[pair]);   // first: unblocks the cam loads
    const int t    = threadIdx.x;
    const int wid  = t >> 5;
    const int lane = t & 31;

    const size_t chan = (size_t)(b * C + lab);
    const float* __restrict__ map = cam + chan * HW;
    const float* __restrict__ pbase = pred_boxes + chan * HW * 4;

    // ---- front-batch cam loads: 2 independent LDG.128 in flight per thread ----
    float4 v4[2];
    #pragma unroll
    for (int it = 0; it < 2; ++it)
        v4[it] = reinterpret_cast<const float4*>(map)[t + it * NT];

    const float4 g = reinterpret_cast<const float4*>(gt_boxes)[pair];
    const float gx1 = g.x, gy1 = g.y, gx2 = g.z, gy2 = g.w;

    const int i_min = max(0,     (int)floorf(gy1 * (float)H));
    const int i_max = min(H - 1, (int)floorf(gy2 * (float)H));
    const int j_min = max(0,     (int)floorf(gx1 * (float)W));
    const int j_max = min(W - 1, (int)floorf(gx2 * (float)W));

    const float thr5 = __ldg(&threshold[0]) * 5.0f;

    float s_tot = 0.f, s_in = 0.f;   // cam sums
    float q_tot = 0.f, q_in = 0.f;   // raw tanh sums (affine-fixed later)
    unsigned long long bkey = 0ull;  // packed argmax key

    #pragma unroll
    for (int it = 0; it < 2; ++it) {
        const int base = (t + it * NT) * 4;
        const int i  = base >> 6;      // row (W = 64)
        const int j0 = base & 63;
        const bool row_in = (i >= i_min) & (i <= i_max);
        const float vv[4] = {v4[it].x, v4[it].y, v4[it].z, v4[it].w};
        #pragma unroll
        for (int e = 0; e < 4; ++e) {
            const float val = vv[e];
            // sigmoid(10*(val-thr)) = 0.5*tanh(5*val - 5*thr) + 0.5 ; 1 MUFU op
            const float th = tanh_fast(fmaf(val, 5.0f, -thr5));
            s_tot += val;
            q_tot += th;
            const int j = j0 + e;
            if (row_in & (j >= j_min) & (j <= j_max)) {
                s_in += val;
                q_in += th;
                const unsigned long long k = pack_key(val, base + e);
                if (k > bkey) bkey = k;
            }
        }
    }

    // ---- warp-level reduction: 4 sums + packed argmax, no barriers ----
    #pragma unroll
    for (int off = 16; off > 0; off >>= 1) {
        s_tot += __shfl_down_sync(0xFFFFFFFFu, s_tot, off);
        s_in  += __shfl_down_sync(0xFFFFFFFFu, s_in,  off);
        q_tot += __shfl_down_sync(0xFFFFFFFFu, q_tot, off);
        q_in  += __shfl_down_sync(0xFFFFFFFFu, q_in,  off);
        const unsigned long long ok = __shfl_down_sync(0xFFFFFFFFu, bkey, off);
        if (ok > bkey) bkey = ok;
    }

    // ---- warp leaders prefetch their candidate pred box into L1 ----
    // The block winner is one of these 16 candidates, so the final gather hits L1.
    if (lane == 0) {
        const int ci = min(key_idx(bkey), HW - 1);   // clamp (empty-mask safety)
        asm volatile("prefetch.global.L1 [%0];" :: "l"(pbase + (size_t)ci * 4));
    }

    // ---- cross-warp combine (16 warps) via shared, one barrier ----
    __shared__ float sh_stot[16], sh_sin[16], sh_qtot[16], sh_qin[16];
    __shared__ unsigned long long sh_bk[16];
    if (lane == 0) {
        sh_stot[wid] = s_tot; sh_sin[wid] = s_in;
        sh_qtot[wid] = q_tot; sh_qin[wid] = q_in;
        sh_bk[wid] = bkey;
    }
    __syncthreads();

    __shared__ bool s_last;
    if (wid == 0) {
        float a_stot = (lane < 16) ? sh_stot[lane] : 0.f;
        float a_sin  = (lane < 16) ? sh_sin[lane]  : 0.f;
        float a_qtot = (lane < 16) ? sh_qtot[lane] : 0.f;
        float a_qin  = (lane < 16) ? sh_qin[lane]  : 0.f;
        unsigned long long a_bk = (lane < 16) ? sh_bk[lane] : 0ull;
        #pragma unroll
        for (int off = 8; off > 0; off >>= 1) {
            a_stot += __shfl_down_sync(0xFFFFFFFFu, a_stot, off);
            a_sin  += __shfl_down_sync(0xFFFFFFFFu, a_sin,  off);
            a_qtot += __shfl_down_sync(0xFFFFFFFFu, a_qtot, off);
            a_qin  += __shfl_down_sync(0xFFFFFFFFu, a_qin,  off);
            const unsigned long long ok = __shfl_down_sync(0xFFFFFFFFu, a_bk, off);
            if (ok > a_bk) a_bk = ok;
        }

        if (lane == 0) {
            // Issue the (L1-resident) winning gather FIRST, overlap with term math.
            const int bi = min(key_idx(a_bk), HW - 1);
            const float4 pbv = *reinterpret_cast<const float4*>(pbase + (size_t)bi * 4);

            const int   cnt   = (i_max - i_min + 1) * (j_max - j_min + 1);
            const float cnt_f = (float)cnt;
            const float out_f = (float)(HW - cnt);

            // Reconstruct sigmoid sums from tanh sums: P = 0.5*Q + 0.5*count
            const float P_tot = 0.5f * a_qtot + 0.5f * (float)HW;
            const float P_in  = 0.5f * a_qin  + 0.5f * cnt_f;

            const float v_in  = a_sin / fmaxf(cnt_f, 1.0f);
            const float v_out = (a_stot - a_sin) / fmaxf(out_f, 1.0f);
            const float term_cam = (cnt > 0 ? 1.0f - v_in : 0.0f) +
                                   (cnt < HW ? v_out : 0.0f);

            const float pv_in  = P_in / fmaxf(cnt_f, 1.0f);
            const float pv_out = (P_tot - P_in) / fmaxf(out_f, 1.0f);
            const float term_peak = (cnt > 0 ? 1.0f - pv_in : 0.0f) +
                                    (cnt < HW ? pv_out : 0.0f);

            const float px1 = pbv.x, py1 = pbv.y, px2 = pbv.z, py2 = pbv.w;

            const float l1 = fabsf(px1 - gx1) + fabsf(py1 - gy1) +
                             fabsf(px2 - gx2) + fabsf(py2 - gy2);

            const float ltx = fmaxf(px1, gx1), lty = fmaxf(py1, gy1);
            const float rbx = fminf(px2, gx2), rby = fminf(py2, gy2);
            const float iw  = fmaxf(rbx - ltx, 0.0f), ih = fmaxf(rby - lty, 0.0f);
            const float inter = iw * ih;
            const float ap = (px2 - px1) * (py2 - py1);
            const float ag = (gx2 - gx1) * (gy2 - gy1);
            const float uni = ap + ag - inter;
            const float iou = inter / uni;
            const float cx1 = fminf(px1, gx1), cy1 = fminf(py1, gy1);
            const float cx2 = fmaxf(px2, gx2), cy2 = fmaxf(py2, gy2);
            const float cw = fmaxf(cx2 - cx1, 0.0f), ch = fmaxf(cy2 - cy1, 0.0f);
            const float ac = cw * ch;
            const float giou = iou - (ac - uni) / ac;

            const float inv = 1.0f / (float)NPAIR;
            g_partial[pair] = (l1 * 0.25f +
                               2.0f * (1.0f - giou) +
                               0.5f * term_cam +
                               0.5f * term_peak) * inv;

            // Release-add orders the partial store; acquire half synchronizes
            // the last block (release sequence on g_done).
            unsigned int prev;
            asm volatile("atom.acq_rel.gpu.global.add.u32 %0, [%1], 1;"
                         : "=r"(prev) : "l"(&g_done) : "memory");
            s_last = (prev == (unsigned int)(NPAIR - 1));
        }
    }
    __syncthreads();

    // ---- last block: deterministic 320-way final sum (shuffle-based) ----
    if (s_last) {
        float v = (t < NPAIR) ? g_partial[t] : 0.0f;   // NPAIR=320 < NT=512
        #pragma unroll
        for (int off = 16; off > 0; off >>= 1)
            v += __shfl_down_sync(0xFFFFFFFFu, v, off);
        __shared__ float sh_f[16];
        if (lane == 0) sh_f[wid] = v;
        __syncthreads();
        if (wid == 0) {
            float a = (lane < 16) ? sh_f[lane] : 0.f;
            #pragma unroll
            for (int off = 8; off > 0; off >>= 1)
                a += __shfl_down_sync(0xFFFFFFFFu, a, off);
            if (lane == 0) {
                g_done = 0;                       // reset for next replay
                sh_f[0] = a;
            }
        }
        __syncthreads();
        for (int i = t; i < out_size; i += NT) out[i] = sh_f[0];
    }
}

extern "C" void kernel_launch(void* const* d_in, const int* in_sizes, int n_in,
                              void* d_out, int out_size)
{
    const float* cam        = nullptr;
    const float* pred_boxes = nullptr;
    const float* gt_boxes   = nullptr;
    const int*   gt_labels  = nullptr;
    const float* threshold  = nullptr;

    for (int i = 0; i < n_in; ++i) {
        switch (in_sizes[i]) {
            case B * C * H * W:       cam        = (const float*)d_in[i]; break;
            case B * C * H * W * 4:   pred_boxes = (const float*)d_in[i]; break;
            case B * K * 4:           gt_boxes   = (const float*)d_in[i]; break;
            case B * K:               gt_labels  = (const int*)d_in[i];   break;
            case 1:                   threshold  = (const float*)d_in[i]; break;
            default: break;
        }
    }

    fused_kernel<<<NPAIR, NT>>>(cam, pred_boxes, gt_boxes, gt_labels, threshold,
                                (float*)d_out, out_size);
}

// round 16
// speedup vs baseline: 1.0221x; 1.0221x over previous
#include <cuda_runtime.h>
#include <math.h>

constexpr int B = 16, C = 80, H = 64, W = 64, K = 20;
constexpr int HW = H * W;          // 4096
constexpr int NPAIR = B * K;       // 320
constexpr int NT = 512;            // threads per block (16 warps)
// PEAK_TEMP = 10: sigmoid(10*(v-thr)) = 0.5*tanh(5*(v-thr)) + 0.5

__device__ float g_partial[NPAIR];
__device__ unsigned int g_done = 0;   // completion counter (reset by last block)

__device__ __forceinline__ float tanh_fast(float x) {
    float y;
    asm("tanh.approx.f32 %0, %1;" : "=f"(y) : "f"(x));
    return y;
}

// Argmax key packing: cam values are >= 0, so raw float bits are monotonic.
// key = (val_bits << 32) | (0xFFFFFFFF - idx): max key == max val, ties -> min idx
// (== first occurrence, matching jnp.argmax). Init key 0 decodes to a huge idx
// that loses any tie; if the mask were empty the gather index clamps safely.
__device__ __forceinline__ unsigned long long pack_key(float v, int idx) {
    return ((unsigned long long)__float_as_uint(v) << 32) |
           (unsigned long long)(0xFFFFFFFFu - (unsigned int)idx);
}
__device__ __forceinline__ int key_idx(unsigned long long k) {
    return (int)(0xFFFFFFFFu - (unsigned int)(k & 0xFFFFFFFFull));
}

// One block per (b,k) pair; LAST block to finish also does the final sum.
__global__ __launch_bounds__(NT) void fused_kernel(
    const float* __restrict__ cam,         // [B,C,H,W]
    const float* __restrict__ pred_boxes,  // [B,C,H,W,4]
    const float* __restrict__ gt_boxes,    // [B,K,4]
    const int*   __restrict__ gt_labels,   // [B,K]
    const float* __restrict__ threshold,   // [1]
    float* __restrict__ out, int out_size)
{
    const int pair = blockIdx.x;
    const int b    = pair / K;
    const int lab  = __ldg(&gt_labels[pair]);   // first: unblocks the cam loads
    const int t    = threadIdx.x;
    const int wid  = t >> 5;
    const int lane = t & 31;

    const size_t chan = (size_t)(b * C + lab);
    const float* __restrict__ map = cam + chan * HW;
    const float* __restrict__ pbase = pred_boxes + chan * HW * 4;

    // ---- front-batch cam loads: 2 independent LDG.128 in flight per thread ----
    float4 v4[2];
    #pragma unroll
    for (int it = 0; it < 2; ++it)
        v4[it] = reinterpret_cast<const float4*>(map)[t + it * NT];

    const float4 g = reinterpret_cast<const float4*>(gt_boxes)[pair];
    const float gx1 = g.x, gy1 = g.y, gx2 = g.z, gy2 = g.w;

    const int i_min = max(0,     (int)floorf(gy1 * (float)H));
    const int i_max = min(H - 1, (int)floorf(gy2 * (float)H));
    const int j_min = max(0,     (int)floorf(gx1 * (float)W));
    const int j_max = min(W - 1, (int)floorf(gx2 * (float)W));

    const float thr5 = __ldg(&threshold[0]) * 5.0f;

    float s_tot = 0.f, s_in = 0.f;   // cam sums
    float q_tot = 0.f, q_in = 0.f;   // raw tanh sums (affine-fixed later)
    unsigned long long bkey = 0ull;  // packed argmax key

    #pragma unroll
    for (int it = 0; it < 2; ++it) {
        const int base = (t + it * NT) * 4;
        const int i  = base >> 6;      // row (W = 64)
        const int j0 = base & 63;
        const bool row_in = (i >= i_min) & (i <= i_max);
        const float vv[4] = {v4[it].x, v4[it].y, v4[it].z, v4[it].w};
        #pragma unroll
        for (int e = 0; e < 4; ++e) {
            const float val = vv[e];
            // sigmoid(10*(val-thr)) = 0.5*tanh(5*val - 5*thr) + 0.5 ; 1 MUFU op
            const float th = tanh_fast(fmaf(val, 5.0f, -thr5));
            s_tot += val;
            q_tot += th;
            const int j = j0 + e;
            if (row_in & (j >= j_min) & (j <= j_max)) {
                s_in += val;
                q_in += th;
                const unsigned long long k = pack_key(val, base + e);
                if (k > bkey) bkey = k;
            }
        }
    }

    // ---- warp-level reduction: 4 sums + packed argmax, no barriers ----
    #pragma unroll
    for (int off = 16; off > 0; off >>= 1) {
        s_tot += __shfl_down_sync(0xFFFFFFFFu, s_tot, off);
        s_in  += __shfl_down_sync(0xFFFFFFFFu, s_in,  off);
        q_tot += __shfl_down_sync(0xFFFFFFFFu, q_tot, off);
        q_in  += __shfl_down_sync(0xFFFFFFFFu, q_in,  off);
        const unsigned long long ok = __shfl_down_sync(0xFFFFFFFFu, bkey, off);
        if (ok > bkey) bkey = ok;
    }

    // ---- warp leaders prefetch their candidate pred box into L1 ----
    // The block winner is one of these 16 candidates, so the final gather hits L1.
    if (lane == 0) {
        const int ci = min(key_idx(bkey), HW - 1);   // clamp (empty-mask safety)
        asm volatile("prefetch.global.L1 [%0];" :: "l"(pbase + (size_t)ci * 4));
    }

    // ---- cross-warp combine (16 warps) via shared, one barrier ----
    __shared__ float sh_stot[16], sh_sin[16], sh_qtot[16], sh_qin[16];
    __shared__ unsigned long long sh_bk[16];
    if (lane == 0) {
        sh_stot[wid] = s_tot; sh_sin[wid] = s_in;
        sh_qtot[wid] = q_tot; sh_qin[wid] = q_in;
        sh_bk[wid] = bkey;
    }
    __syncthreads();

    __shared__ bool s_last;
    if (wid == 0) {
        float a_stot = (lane < 16) ? sh_stot[lane] : 0.f;
        float a_sin  = (lane < 16) ? sh_sin[lane]  : 0.f;
        float a_qtot = (lane < 16) ? sh_qtot[lane] : 0.f;
        float a_qin  = (lane < 16) ? sh_qin[lane]  : 0.f;
        unsigned long long a_bk = (lane < 16) ? sh_bk[lane] : 0ull;
        #pragma unroll
        for (int off = 8; off > 0; off >>= 1) {
            a_stot += __shfl_down_sync(0xFFFFFFFFu, a_stot, off);
            a_sin  += __shfl_down_sync(0xFFFFFFFFu, a_sin,  off);
            a_qtot += __shfl_down_sync(0xFFFFFFFFu, a_qtot, off);
            a_qin  += __shfl_down_sync(0xFFFFFFFFu, a_qin,  off);
            const unsigned long long ok = __shfl_down_sync(0xFFFFFFFFu, a_bk, off);
            if (ok > a_bk) a_bk = ok;
        }

        if (lane == 0) {
            // Issue the (L1-resident) winning gather FIRST, overlap with term math.
            const int bi = min(key_idx(a_bk), HW - 1);
            const float4 pbv = *reinterpret_cast<const float4*>(pbase + (size_t)bi * 4);

            const int   cnt   = (i_max - i_min + 1) * (j_max - j_min + 1);
            const float cnt_f = (float)cnt;
            const float out_f = (float)(HW - cnt);

            // Reconstruct sigmoid sums from tanh sums: P = 0.5*Q + 0.5*count
            const float P_tot = 0.5f * a_qtot + 0.5f * (float)HW;
            const float P_in  = 0.5f * a_qin  + 0.5f * cnt_f;

            const float v_in  = a_sin / fmaxf(cnt_f, 1.0f);
            const float v_out = (a_stot - a_sin) / fmaxf(out_f, 1.0f);
            const float term_cam = (cnt > 0 ? 1.0f - v_in : 0.0f) +
                                   (cnt < HW ? v_out : 0.0f);

            const float pv_in  = P_in / fmaxf(cnt_f, 1.0f);
            const float pv_out = (P_tot - P_in) / fmaxf(out_f, 1.0f);
            const float term_peak = (cnt > 0 ? 1.0f - pv_in : 0.0f) +
                                    (cnt < HW ? pv_out : 0.0f);

            const float px1 = pbv.x, py1 = pbv.y, px2 = pbv.z, py2 = pbv.w;

            const float l1 = fabsf(px1 - gx1) + fabsf(py1 - gy1) +
                             fabsf(px2 - gx2) + fabsf(py2 - gy2);

            const float ltx = fmaxf(px1, gx1), lty = fmaxf(py1, gy1);
            const float rbx = fminf(px2, gx2), rby = fminf(py2, gy2);
            const float iw  = fmaxf(rbx - ltx, 0.0f), ih = fmaxf(rby - lty, 0.0f);
            const float inter = iw * ih;
            const float ap = (px2 - px1) * (py2 - py1);
            const float ag = (gx2 - gx1) * (gy2 - gy1);
            const float uni = ap + ag - inter;
            const float iou = inter / uni;
            const float cx1 = fminf(px1, gx1), cy1 = fminf(py1, gy1);
            const float cx2 = fmaxf(px2, gx2), cy2 = fmaxf(py2, gy2);
            const float cw = fmaxf(cx2 - cx1, 0.0f), ch = fmaxf(cy2 - cy1, 0.0f);
            const float ac = cw * ch;
            const float giou = iou - (ac - uni) / ac;

            const float inv = 1.0f / (float)NPAIR;
            g_partial[pair] = (l1 * 0.25f +
                               2.0f * (1.0f - giou) +
                               0.5f * term_cam +
                               0.5f * term_peak) * inv;

            // Release-add orders the partial store; acquire half synchronizes
            // the last block (release sequence on g_done).
            unsigned int prev;
            asm volatile("atom.acq_rel.gpu.global.add.u32 %0, [%1], 1;"
                         : "=r"(prev) : "l"(&g_done) : "memory");
            s_last = (prev == (unsigned int)(NPAIR - 1));
        }
    }
    __syncthreads();

    // ---- last block: deterministic 320-way final sum (shuffle-based) ----
    if (s_last) {
        float v = (t < NPAIR) ? g_partial[t] : 0.0f;   // NPAIR=320 < NT=512
        #pragma unroll
        for (int off = 16; off > 0; off >>= 1)
            v += __shfl_down_sync(0xFFFFFFFFu, v, off);
        __shared__ float sh_f[16];
        if (lane == 0) sh_f[wid] = v;
        __syncthreads();
        if (wid == 0) {
            float a = (lane < 16) ? sh_f[lane] : 0.f;
            #pragma unroll
            for (int off = 8; off > 0; off >>= 1)
                a += __shfl_down_sync(0xFFFFFFFFu, a, off);
            if (lane == 0) {
                g_done = 0;                       // reset for next replay
                sh_f[0] = a;
            }
        }
        __syncthreads();
        for (int i = t; i < out_size; i += NT) out[i] = sh_f[0];
    }
}

extern "C" void kernel_launch(void* const* d_in, const int* in_sizes, int n_in,
                              void* d_out, int out_size)
{
    const float* cam        = nullptr;
    const float* pred_boxes = nullptr;
    const float* gt_boxes   = nullptr;
    const int*   gt_labels  = nullptr;
    const float* threshold  = nullptr;

    for (int i = 0; i < n_in; ++i) {
        switch (in_sizes[i]) {
            case B * C * H * W:       cam        = (const float*)d_in[i]; break;
            case B * C * H * W * 4:   pred_boxes = (const float*)d_in[i]; break;
            case B * K * 4:           gt_boxes   = (const float*)d_in[i]; break;
            case B * K:               gt_labels  = (const int*)d_in[i];   break;
            case 1:                   threshold  = (const float*)d_in[i]; break;
            default: break;
        }
    }

    fused_kernel<<<NPAIR, NT>>>(cam, pred_boxes, gt_boxes, gt_labels, threshold,
                                (float*)d_out, out_size);
}